// round 1
// baseline (speedup 1.0000x reference)
#include <cuda_runtime.h>
#include <math.h>

#define DM 3072
#define BB 2
#define SSEQ 1024
#define NH 24
#define HD 128
#define MROWS (BB*SSEQ)   // 2048

// Scratch (device globals: no allocations allowed)
__device__ float g_q[MROWS*DM];
__device__ float g_k[MROWS*DM];
__device__ float g_v[MROWS*DM];
__device__ float g_ao[MROWS*DM];

// ---------------------------------------------------------------------------
// SGEMM: Y[m,n] = sum_k X[m,k] * W[n,k]   (X row-major [M,K], W row-major [N,K])
// M=2048, N=3072, K=3072. Tiles 128x128x16, 256 threads, 8x8 per thread.
// ---------------------------------------------------------------------------
__global__ __launch_bounds__(256) void sgemm_kernel(
    const float* __restrict__ X, const float* __restrict__ W, float* __restrict__ Y)
{
    __shared__ float As[16][132];
    __shared__ float Bs[16][132];

    const int t  = threadIdx.x;
    const int bm = blockIdx.y * 128;
    const int bn = blockIdx.x * 128;
    const int tx = t & 15;
    const int ty = t >> 4;
    const int lrow = t >> 2;        // 0..63
    const int lk4  = (t & 3) * 4;   // 0,4,8,12

    const float* xp0 = X + (size_t)(bm + lrow)      * DM + lk4;
    const float* xp1 = X + (size_t)(bm + lrow + 64) * DM + lk4;
    const float* wp0 = W + (size_t)(bn + lrow)      * DM + lk4;
    const float* wp1 = W + (size_t)(bn + lrow + 64) * DM + lk4;

    float4 ax0 = *(const float4*)xp0;
    float4 ax1 = *(const float4*)xp1;
    float4 bx0 = *(const float4*)wp0;
    float4 bx1 = *(const float4*)wp1;

    float c[8][8];
    #pragma unroll
    for (int i = 0; i < 8; i++)
        #pragma unroll
        for (int j = 0; j < 8; j++) c[i][j] = 0.f;

    const int NKT = DM / 16;  // 192
    for (int kt = 0; kt < NKT; kt++) {
        As[lk4+0][lrow]    = ax0.x; As[lk4+1][lrow]    = ax0.y;
        As[lk4+2][lrow]    = ax0.z; As[lk4+3][lrow]    = ax0.w;
        As[lk4+0][lrow+64] = ax1.x; As[lk4+1][lrow+64] = ax1.y;
        As[lk4+2][lrow+64] = ax1.z; As[lk4+3][lrow+64] = ax1.w;
        Bs[lk4+0][lrow]    = bx0.x; Bs[lk4+1][lrow]    = bx0.y;
        Bs[lk4+2][lrow]    = bx0.z; Bs[lk4+3][lrow]    = bx0.w;
        Bs[lk4+0][lrow+64] = bx1.x; Bs[lk4+1][lrow+64] = bx1.y;
        Bs[lk4+2][lrow+64] = bx1.z; Bs[lk4+3][lrow+64] = bx1.w;
        __syncthreads();

        if (kt + 1 < NKT) {
            const int off = (kt + 1) * 16;
            ax0 = *(const float4*)(xp0 + off);
            ax1 = *(const float4*)(xp1 + off);
            bx0 = *(const float4*)(wp0 + off);
            bx1 = *(const float4*)(wp1 + off);
        }

        #pragma unroll
        for (int kk = 0; kk < 16; kk++) {
            float4 a0 = *(float4*)&As[kk][ty*8];
            float4 a1 = *(float4*)&As[kk][ty*8+4];
            float4 b0 = *(float4*)&Bs[kk][tx*8];
            float4 b1 = *(float4*)&Bs[kk][tx*8+4];
            float av[8] = {a0.x,a0.y,a0.z,a0.w,a1.x,a1.y,a1.z,a1.w};
            float bv[8] = {b0.x,b0.y,b0.z,b0.w,b1.x,b1.y,b1.z,b1.w};
            #pragma unroll
            for (int i = 0; i < 8; i++)
                #pragma unroll
                for (int j = 0; j < 8; j++)
                    c[i][j] += av[i] * bv[j];
        }
        __syncthreads();
    }

    #pragma unroll
    for (int i = 0; i < 8; i++) {
        float* yp = Y + (size_t)(bm + ty*8 + i) * DM + bn + tx*8;
        float4 o0 = {c[i][0], c[i][1], c[i][2], c[i][3]};
        float4 o1 = {c[i][4], c[i][5], c[i][6], c[i][7]};
        *(float4*)yp       = o0;
        *(float4*)(yp + 4) = o1;
    }
}

// ---------------------------------------------------------------------------
// Fused RMSNorm + RoPE on q and k. One block per (b*S+s, h), 128 threads.
// ---------------------------------------------------------------------------
__global__ __launch_bounds__(128) void norm_rope_kernel(
    float* __restrict__ q, float* __restrict__ k,
    const float* __restrict__ rope,
    const float* __restrict__ wq, const float* __restrict__ wk)
{
    const int row = blockIdx.x;      // b*S + s
    const int h   = blockIdx.y;
    const int d   = threadIdx.x;     // 0..127
    const int s   = row & (SSEQ - 1);

    __shared__ float sh[128];
    __shared__ float red[4];

    float fr = rope[s * HD + d];
    float cs, sn;
    sincosf(fr, &sn, &cs);   // note: sincosf(x, &sin, &cos)

    #pragma unroll
    for (int which = 0; which < 2; which++) {
        float* base = (which ? k : q) + (size_t)row * DM + h * HD;
        const float* w = which ? wk : wq;

        float x = base[d];
        float ssum = x * x;
        #pragma unroll
        for (int o = 16; o > 0; o >>= 1)
            ssum += __shfl_xor_sync(0xffffffffu, ssum, o);
        if ((d & 31) == 0) red[d >> 5] = ssum;
        __syncthreads();
        float tot = red[0] + red[1] + red[2] + red[3];
        float xn = x * rsqrtf(tot * (1.f/128.f) + 1e-6f) * w[d];
        sh[d] = xn;
        __syncthreads();
        float rot = (d < 64) ? -sh[d + 64] : sh[d - 64];
        base[d] = xn * cs + rot * sn;
        __syncthreads();
    }
}

// ---------------------------------------------------------------------------
// Flash-style attention. Block = 256 threads, 64 q-rows, loop over 16 k-tiles.
// Smem: Qst[128][68] (transposed), KVs[128][68] (K transposed / V row-major),
//       Ss[64][68] (scores / probs).
// ---------------------------------------------------------------------------
#define ATT_PAD 68
#define ATT_SMEM ((2*128*ATT_PAD + 64*ATT_PAD) * 4)

__global__ __launch_bounds__(256) void attn_kernel(
    const float* __restrict__ Q, const float* __restrict__ K,
    const float* __restrict__ V, float* __restrict__ O)
{
    extern __shared__ float smbuf[];
    float* Qst = smbuf;
    float* KVs = smbuf + 128 * ATT_PAD;
    float* Ss  = smbuf + 2 * 128 * ATT_PAD;

    const int t  = threadIdx.x;
    const int qt = blockIdx.x;           // 0..15
    const int bh = blockIdx.y;           // 0..47
    const int b  = bh / NH;
    const int h  = bh % NH;
    const size_t base = (size_t)b * SSEQ * DM + (size_t)h * HD;
    const float* qb = Q + base;
    const float* kb = K + base;
    const float* vb = V + base;
    const int q0 = qt * 64;

    // Load Q tile, transposed (row per lane -> conflict-free STS)
    #pragma unroll
    for (int it = 0; it < 8; it++) {
        int f   = t + it * 256;
        int row = f & 63;
        int d0  = (f >> 6) * 4;
        float4 v4 = *(const float4*)(qb + (size_t)(q0 + row) * DM + d0);
        Qst[(d0+0)*ATT_PAD + row] = v4.x;
        Qst[(d0+1)*ATT_PAD + row] = v4.y;
        Qst[(d0+2)*ATT_PAD + row] = v4.z;
        Qst[(d0+3)*ATT_PAD + row] = v4.w;
    }

    const int ty = t >> 4, tx = t & 15;  // S-compute mapping (4x4 frags)
    const int g  = t >> 2, q4 = t & 3;   // softmax/PV mapping (row g, lane q4)

    float acc[32];
    #pragma unroll
    for (int j = 0; j < 32; j++) acc[j] = 0.f;
    float m_r = -1e30f, l_r = 0.f;
    const float scale = 0.08838834764831845f;  // 1/sqrt(128)

    for (int kt = 0; kt < 16; kt++) {
        __syncthreads();   // covers Q load (kt=0) and prior-iter PV reads
        const int k0 = kt * 64;

        // Load K tile, transposed
        #pragma unroll
        for (int it = 0; it < 8; it++) {
            int f   = t + it * 256;
            int row = f & 63;
            int d0  = (f >> 6) * 4;
            float4 v4 = *(const float4*)(kb + (size_t)(k0 + row) * DM + d0);
            KVs[(d0+0)*ATT_PAD + row] = v4.x;
            KVs[(d0+1)*ATT_PAD + row] = v4.y;
            KVs[(d0+2)*ATT_PAD + row] = v4.z;
            KVs[(d0+3)*ATT_PAD + row] = v4.w;
        }
        __syncthreads();

        // S = Q @ K^T : each thread computes 4x4
        float cf[4][4];
        #pragma unroll
        for (int i = 0; i < 4; i++)
            #pragma unroll
            for (int j = 0; j < 4; j++) cf[i][j] = 0.f;

        #pragma unroll 8
        for (int d = 0; d < 128; d++) {
            float4 qa = *(float4*)&Qst[d*ATT_PAD + ty*4];
            float4 ka = *(float4*)&KVs[d*ATT_PAD + tx*4];
            float av[4] = {qa.x, qa.y, qa.z, qa.w};
            float bv[4] = {ka.x, ka.y, ka.z, ka.w};
            #pragma unroll
            for (int i = 0; i < 4; i++)
                #pragma unroll
                for (int j = 0; j < 4; j++)
                    cf[i][j] += av[i] * bv[j];
        }
        #pragma unroll
        for (int i = 0; i < 4; i++) {
            float4 sv = {cf[i][0]*scale, cf[i][1]*scale, cf[i][2]*scale, cf[i][3]*scale};
            *(float4*)&Ss[(ty*4+i)*ATT_PAD + tx*4] = sv;
        }
        __syncthreads();

        // Online softmax for row g (4 lanes per row)
        float tmax = -1e30f;
        #pragma unroll
        for (int kk = q4; kk < 64; kk += 4)
            tmax = fmaxf(tmax, Ss[g*ATT_PAD + kk]);
        tmax = fmaxf(tmax, __shfl_xor_sync(0xffffffffu, tmax, 1));
        tmax = fmaxf(tmax, __shfl_xor_sync(0xffffffffu, tmax, 2));
        float mnew  = fmaxf(m_r, tmax);
        float alpha = __expf(m_r - mnew);
        float psum  = 0.f;
        #pragma unroll
        for (int kk = q4; kk < 64; kk += 4) {
            float p = __expf(Ss[g*ATT_PAD + kk] - mnew);
            Ss[g*ATT_PAD + kk] = p;
            psum += p;
        }
        psum += __shfl_xor_sync(0xffffffffu, psum, 1);
        psum += __shfl_xor_sync(0xffffffffu, psum, 2);
        l_r = l_r * alpha + psum;
        m_r = mnew;
        #pragma unroll
        for (int j = 0; j < 32; j++) acc[j] *= alpha;

        // Load V tile row-major into KVs (K no longer needed)
        #pragma unroll
        for (int it = 0; it < 8; it++) {
            int f   = t + it * 256;
            int row = f >> 5;
            int d0  = (f & 31) * 4;
            float4 v4 = *(const float4*)(vb + (size_t)(k0 + row) * DM + d0);
            *(float4*)&KVs[row*128 + d0] = v4;
        }
        __syncthreads();

        // acc += P @ V  (thread owns row g, cols jj*16 + q4*4 + 0..3)
        #pragma unroll 4
        for (int kk = 0; kk < 64; kk++) {
            float p = Ss[g*ATT_PAD + kk];
            #pragma unroll
            for (int jj = 0; jj < 8; jj++) {
                float4 v4 = *(float4*)&KVs[kk*128 + jj*16 + q4*4];
                acc[jj*4+0] += p * v4.x;
                acc[jj*4+1] += p * v4.y;
                acc[jj*4+2] += p * v4.z;
                acc[jj*4+3] += p * v4.w;
            }
        }
    }

    const float inv = 1.f / l_r;
    float* ob = O + base + (size_t)(q0 + g) * DM;
    #pragma unroll
    for (int jj = 0; jj < 8; jj++) {
        float4 o4 = {acc[jj*4+0]*inv, acc[jj*4+1]*inv, acc[jj*4+2]*inv, acc[jj*4+3]*inv};
        *(float4*)&ob[jj*16 + q4*4] = o4;
    }
}

// ---------------------------------------------------------------------------
extern "C" void kernel_launch(void* const* d_in, const int* in_sizes, int n_in,
                              void* d_out, int out_size)
{
    const float* hidden = (const float*)d_in[0];
    const float* rope   = (const float*)d_in[1];
    const float* Wq     = (const float*)d_in[2];
    const float* Wk     = (const float*)d_in[3];
    const float* Wv     = (const float*)d_in[4];
    const float* Wo     = (const float*)d_in[5];
    const float* nqw    = (const float*)d_in[6];
    const float* nkw    = (const float*)d_in[7];
    float* out = (float*)d_out;

    float *q, *k, *v, *ao;
    cudaGetSymbolAddress((void**)&q,  g_q);
    cudaGetSymbolAddress((void**)&k,  g_k);
    cudaGetSymbolAddress((void**)&v,  g_v);
    cudaGetSymbolAddress((void**)&ao, g_ao);

    dim3 gg(DM/128, MROWS/128);  // (24, 16)
    sgemm_kernel<<<gg, 256>>>(hidden, Wq, q);
    sgemm_kernel<<<gg, 256>>>(hidden, Wk, k);
    sgemm_kernel<<<gg, 256>>>(hidden, Wv, v);

    norm_rope_kernel<<<dim3(MROWS, NH), 128>>>(q, k, rope, nqw, nkw);

    cudaFuncSetAttribute(attn_kernel, cudaFuncAttributeMaxDynamicSharedMemorySize, ATT_SMEM);
    attn_kernel<<<dim3(SSEQ/64, BB*NH), 256, ATT_SMEM>>>(q, k, v, ao);

    sgemm_kernel<<<gg, 256>>>(ao, Wo, out);
}

// round 2
// speedup vs baseline: 1.8142x; 1.8142x over previous
#include <cuda_runtime.h>
#include <math.h>
#include <stdint.h>

#define DM 3072
#define BB 2
#define SSEQ 1024
#define NH 24
#define HD 128
#define MROWS (BB*SSEQ)   // 2048

// Scratch (device globals: no allocations allowed)
__device__ float g_q[MROWS*DM];
__device__ float g_k[MROWS*DM];
__device__ float g_v[MROWS*DM];
__device__ float g_ao[MROWS*DM];

// ---------------------------------------------------------------------------
// tf32 tensor-core GEMM: Y[m,n] = sum_k X[m,k] * W[n,k]
// X row-major [M,K], W row-major [N,K].  M=2048, N=3072, K=3072.
// CTA tile 128x128x16, 8 warps (4m x 2n), warp tile 32x64.
// mma.sync.aligned.m16n8k8.row.col.f32.tf32.tf32.f32
// ---------------------------------------------------------------------------
#define PADK 20   // smem k-stride (floats): conflict-free fragment LDS

__device__ __forceinline__ uint32_t f2tf32(float x) {
    uint32_t r;
    asm("cvt.rna.tf32.f32 %0, %1;" : "=r"(r) : "f"(x));
    return r;
}

__device__ __forceinline__ void mma_tf32(float c[4],
    uint32_t a0, uint32_t a1, uint32_t a2, uint32_t a3,
    uint32_t b0, uint32_t b1)
{
    asm volatile(
        "mma.sync.aligned.m16n8k8.row.col.f32.tf32.tf32.f32 "
        "{%0,%1,%2,%3}, {%4,%5,%6,%7}, {%8,%9}, {%0,%1,%2,%3};"
        : "+f"(c[0]), "+f"(c[1]), "+f"(c[2]), "+f"(c[3])
        : "r"(a0), "r"(a1), "r"(a2), "r"(a3), "r"(b0), "r"(b1));
}

__global__ __launch_bounds__(256) void tf32_gemm_kernel(
    const float* __restrict__ X, const float* __restrict__ W, float* __restrict__ Y)
{
    __shared__ uint32_t As[128 * PADK];
    __shared__ uint32_t Bs[128 * PADK];

    const int t    = threadIdx.x;
    const int lane = t & 31;
    const int w    = t >> 5;
    const int warp_m = (w >> 1) * 32;   // 0,32,64,96
    const int warp_n = (w & 1) * 64;    // 0,64
    const int bm = blockIdx.y * 128;
    const int bn = blockIdx.x * 128;

    const int lrow = t >> 2;      // 0..63
    const int lc4  = (t & 3) * 4; // 0,4,8,12

    const float* xp = X + (size_t)(bm + lrow) * DM + lc4;
    const float* wp = W + (size_t)(bn + lrow) * DM + lc4;

    float4 ax0 = *(const float4*)(xp);
    float4 ax1 = *(const float4*)(xp + (size_t)64 * DM);
    float4 bx0 = *(const float4*)(wp);
    float4 bx1 = *(const float4*)(wp + (size_t)64 * DM);

    float c[2][8][4];
    #pragma unroll
    for (int mi = 0; mi < 2; mi++)
        #pragma unroll
        for (int ni = 0; ni < 8; ni++)
            #pragma unroll
            for (int j = 0; j < 4; j++) c[mi][ni][j] = 0.f;

    const int qd = lane >> 2;  // 0..7
    const int qk = lane & 3;   // 0..3
    const int NKT = DM / 16;   // 192

    for (int kt = 0; kt < NKT; kt++) {
        __syncthreads();   // previous iter's smem reads complete
        As[lrow*PADK + lc4 + 0] = f2tf32(ax0.x);
        As[lrow*PADK + lc4 + 1] = f2tf32(ax0.y);
        As[lrow*PADK + lc4 + 2] = f2tf32(ax0.z);
        As[lrow*PADK + lc4 + 3] = f2tf32(ax0.w);
        As[(lrow+64)*PADK + lc4 + 0] = f2tf32(ax1.x);
        As[(lrow+64)*PADK + lc4 + 1] = f2tf32(ax1.y);
        As[(lrow+64)*PADK + lc4 + 2] = f2tf32(ax1.z);
        As[(lrow+64)*PADK + lc4 + 3] = f2tf32(ax1.w);
        Bs[lrow*PADK + lc4 + 0] = f2tf32(bx0.x);
        Bs[lrow*PADK + lc4 + 1] = f2tf32(bx0.y);
        Bs[lrow*PADK + lc4 + 2] = f2tf32(bx0.z);
        Bs[lrow*PADK + lc4 + 3] = f2tf32(bx0.w);
        Bs[(lrow+64)*PADK + lc4 + 0] = f2tf32(bx1.x);
        Bs[(lrow+64)*PADK + lc4 + 1] = f2tf32(bx1.y);
        Bs[(lrow+64)*PADK + lc4 + 2] = f2tf32(bx1.z);
        Bs[(lrow+64)*PADK + lc4 + 3] = f2tf32(bx1.w);
        __syncthreads();

        if (kt + 1 < NKT) {
            const int off = (kt + 1) * 16;
            ax0 = *(const float4*)(xp + off);
            ax1 = *(const float4*)(xp + (size_t)64 * DM + off);
            bx0 = *(const float4*)(wp + off);
            bx1 = *(const float4*)(wp + (size_t)64 * DM + off);
        }

        #pragma unroll
        for (int ks = 0; ks < 2; ks++) {
            const int k0 = ks * 8 + qk;
            uint32_t a[2][4];
            #pragma unroll
            for (int mi = 0; mi < 2; mi++) {
                const int r0 = warp_m + mi*16 + qd;
                a[mi][0] = As[r0*PADK + k0];
                a[mi][1] = As[(r0+8)*PADK + k0];
                a[mi][2] = As[r0*PADK + k0 + 4];
                a[mi][3] = As[(r0+8)*PADK + k0 + 4];
            }
            #pragma unroll
            for (int ni = 0; ni < 8; ni++) {
                const int cn = warp_n + ni*8 + qd;
                uint32_t b0 = Bs[cn*PADK + k0];
                uint32_t b1 = Bs[cn*PADK + k0 + 4];
                mma_tf32(c[0][ni], a[0][0], a[0][1], a[0][2], a[0][3], b0, b1);
                mma_tf32(c[1][ni], a[1][0], a[1][1], a[1][2], a[1][3], b0, b1);
            }
        }
    }

    // Write results: c layout — row = warp_m+mi*16+qd (+8 for c[2],c[3]),
    // col = warp_n+ni*8+qk*2 (+1)
    #pragma unroll
    for (int mi = 0; mi < 2; mi++) {
        #pragma unroll
        for (int ni = 0; ni < 8; ni++) {
            const int row = bm + warp_m + mi*16 + qd;
            const int col = bn + warp_n + ni*8 + qk*2;
            float2 v0 = {c[mi][ni][0], c[mi][ni][1]};
            float2 v1 = {c[mi][ni][2], c[mi][ni][3]};
            *(float2*)(Y + (size_t)row * DM + col)       = v0;
            *(float2*)(Y + (size_t)(row + 8) * DM + col) = v1;
        }
    }
}

// ---------------------------------------------------------------------------
// Fused RMSNorm + RoPE on q and k. One block per (b*S+s, h), 128 threads.
// ---------------------------------------------------------------------------
__global__ __launch_bounds__(128) void norm_rope_kernel(
    float* __restrict__ q, float* __restrict__ k,
    const float* __restrict__ rope,
    const float* __restrict__ wq, const float* __restrict__ wk)
{
    const int row = blockIdx.x;      // b*S + s
    const int h   = blockIdx.y;
    const int d   = threadIdx.x;     // 0..127
    const int s   = row & (SSEQ - 1);

    __shared__ float sh[128];
    __shared__ float red[4];

    float fr = rope[s * HD + d];
    float cs, sn;
    sincosf(fr, &sn, &cs);

    #pragma unroll
    for (int which = 0; which < 2; which++) {
        float* base = (which ? k : q) + (size_t)row * DM + h * HD;
        const float* w = which ? wk : wq;

        float x = base[d];
        float ssum = x * x;
        #pragma unroll
        for (int o = 16; o > 0; o >>= 1)
            ssum += __shfl_xor_sync(0xffffffffu, ssum, o);
        if ((d & 31) == 0) red[d >> 5] = ssum;
        __syncthreads();
        float tot = red[0] + red[1] + red[2] + red[3];
        float xn = x * rsqrtf(tot * (1.f/128.f) + 1e-6f) * w[d];
        sh[d] = xn;
        __syncthreads();
        float rot = (d < 64) ? -sh[d + 64] : sh[d - 64];
        base[d] = xn * cs + rot * sn;
        __syncthreads();
    }
}

// ---------------------------------------------------------------------------
// Flash-style attention (fp32 SIMT). Block = 256 threads, 64 q-rows.
// ---------------------------------------------------------------------------
#define ATT_PAD 68
#define ATT_SMEM ((2*128*ATT_PAD + 64*ATT_PAD) * 4)

__global__ __launch_bounds__(256) void attn_kernel(
    const float* __restrict__ Q, const float* __restrict__ K,
    const float* __restrict__ V, float* __restrict__ O)
{
    extern __shared__ float smbuf[];
    float* Qst = smbuf;
    float* KVs = smbuf + 128 * ATT_PAD;
    float* Ss  = smbuf + 2 * 128 * ATT_PAD;

    const int t  = threadIdx.x;
    const int qt = blockIdx.x;           // 0..15
    const int bh = blockIdx.y;           // 0..47
    const int b  = bh / NH;
    const int h  = bh % NH;
    const size_t base = (size_t)b * SSEQ * DM + (size_t)h * HD;
    const float* qb = Q + base;
    const float* kb = K + base;
    const float* vb = V + base;
    const int q0 = qt * 64;

    #pragma unroll
    for (int it = 0; it < 8; it++) {
        int f   = t + it * 256;
        int row = f & 63;
        int d0  = (f >> 6) * 4;
        float4 v4 = *(const float4*)(qb + (size_t)(q0 + row) * DM + d0);
        Qst[(d0+0)*ATT_PAD + row] = v4.x;
        Qst[(d0+1)*ATT_PAD + row] = v4.y;
        Qst[(d0+2)*ATT_PAD + row] = v4.z;
        Qst[(d0+3)*ATT_PAD + row] = v4.w;
    }

    const int ty = t >> 4, tx = t & 15;
    const int g  = t >> 2, q4 = t & 3;

    float acc[32];
    #pragma unroll
    for (int j = 0; j < 32; j++) acc[j] = 0.f;
    float m_r = -1e30f, l_r = 0.f;
    const float scale = 0.08838834764831845f;

    for (int kt = 0; kt < 16; kt++) {
        __syncthreads();
        const int k0 = kt * 64;

        #pragma unroll
        for (int it = 0; it < 8; it++) {
            int f   = t + it * 256;
            int row = f & 63;
            int d0  = (f >> 6) * 4;
            float4 v4 = *(const float4*)(kb + (size_t)(k0 + row) * DM + d0);
            KVs[(d0+0)*ATT_PAD + row] = v4.x;
            KVs[(d0+1)*ATT_PAD + row] = v4.y;
            KVs[(d0+2)*ATT_PAD + row] = v4.z;
            KVs[(d0+3)*ATT_PAD + row] = v4.w;
        }
        __syncthreads();

        float cf[4][4];
        #pragma unroll
        for (int i = 0; i < 4; i++)
            #pragma unroll
            for (int j = 0; j < 4; j++) cf[i][j] = 0.f;

        #pragma unroll 8
        for (int d = 0; d < 128; d++) {
            float4 qa = *(float4*)&Qst[d*ATT_PAD + ty*4];
            float4 ka = *(float4*)&KVs[d*ATT_PAD + tx*4];
            float av[4] = {qa.x, qa.y, qa.z, qa.w};
            float bv[4] = {ka.x, ka.y, ka.z, ka.w};
            #pragma unroll
            for (int i = 0; i < 4; i++)
                #pragma unroll
                for (int j = 0; j < 4; j++)
                    cf[i][j] += av[i] * bv[j];
        }
        #pragma unroll
        for (int i = 0; i < 4; i++) {
            float4 sv = {cf[i][0]*scale, cf[i][1]*scale, cf[i][2]*scale, cf[i][3]*scale};
            *(float4*)&Ss[(ty*4+i)*ATT_PAD + tx*4] = sv;
        }
        __syncthreads();

        float tmax = -1e30f;
        #pragma unroll
        for (int kk = q4; kk < 64; kk += 4)
            tmax = fmaxf(tmax, Ss[g*ATT_PAD + kk]);
        tmax = fmaxf(tmax, __shfl_xor_sync(0xffffffffu, tmax, 1));
        tmax = fmaxf(tmax, __shfl_xor_sync(0xffffffffu, tmax, 2));
        float mnew  = fmaxf(m_r, tmax);
        float alpha = __expf(m_r - mnew);
        float psum  = 0.f;
        #pragma unroll
        for (int kk = q4; kk < 64; kk += 4) {
            float p = __expf(Ss[g*ATT_PAD + kk] - mnew);
            Ss[g*ATT_PAD + kk] = p;
            psum += p;
        }
        psum += __shfl_xor_sync(0xffffffffu, psum, 1);
        psum += __shfl_xor_sync(0xffffffffu, psum, 2);
        l_r = l_r * alpha + psum;
        m_r = mnew;
        #pragma unroll
        for (int j = 0; j < 32; j++) acc[j] *= alpha;

        #pragma unroll
        for (int it = 0; it < 8; it++) {
            int f   = t + it * 256;
            int row = f >> 5;
            int d0  = (f & 31) * 4;
            float4 v4 = *(const float4*)(vb + (size_t)(k0 + row) * DM + d0);
            *(float4*)&KVs[row*128 + d0] = v4;
        }
        __syncthreads();

        #pragma unroll 4
        for (int kk = 0; kk < 64; kk++) {
            float p = Ss[g*ATT_PAD + kk];
            #pragma unroll
            for (int jj = 0; jj < 8; jj++) {
                float4 v4 = *(float4*)&KVs[kk*128 + jj*16 + q4*4];
                acc[jj*4+0] += p * v4.x;
                acc[jj*4+1] += p * v4.y;
                acc[jj*4+2] += p * v4.z;
                acc[jj*4+3] += p * v4.w;
            }
        }
    }

    const float inv = 1.f / l_r;
    float* ob = O + base + (size_t)(q0 + g) * DM;
    #pragma unroll
    for (int jj = 0; jj < 8; jj++) {
        float4 o4 = {acc[jj*4+0]*inv, acc[jj*4+1]*inv, acc[jj*4+2]*inv, acc[jj*4+3]*inv};
        *(float4*)&ob[jj*16 + q4*4] = o4;
    }
}

// ---------------------------------------------------------------------------
extern "C" void kernel_launch(void* const* d_in, const int* in_sizes, int n_in,
                              void* d_out, int out_size)
{
    const float* hidden = (const float*)d_in[0];
    const float* rope   = (const float*)d_in[1];
    const float* Wq     = (const float*)d_in[2];
    const float* Wk     = (const float*)d_in[3];
    const float* Wv     = (const float*)d_in[4];
    const float* Wo     = (const float*)d_in[5];
    const float* nqw    = (const float*)d_in[6];
    const float* nkw    = (const float*)d_in[7];
    float* out = (float*)d_out;

    float *q, *k, *v, *ao;
    cudaGetSymbolAddress((void**)&q,  g_q);
    cudaGetSymbolAddress((void**)&k,  g_k);
    cudaGetSymbolAddress((void**)&v,  g_v);
    cudaGetSymbolAddress((void**)&ao, g_ao);

    dim3 gg(DM/128, MROWS/128);  // (24, 16)
    tf32_gemm_kernel<<<gg, 256>>>(hidden, Wq, q);
    tf32_gemm_kernel<<<gg, 256>>>(hidden, Wk, k);
    tf32_gemm_kernel<<<gg, 256>>>(hidden, Wv, v);

    norm_rope_kernel<<<dim3(MROWS, NH), 128>>>(q, k, rope, nqw, nkw);

    cudaFuncSetAttribute(attn_kernel, cudaFuncAttributeMaxDynamicSharedMemorySize, ATT_SMEM);
    attn_kernel<<<dim3(SSEQ/64, BB*NH), 256, ATT_SMEM>>>(q, k, v, ao);

    tf32_gemm_kernel<<<gg, 256>>>(ao, Wo, out);
}

// round 3
// speedup vs baseline: 3.1675x; 1.7459x over previous
#include <cuda_runtime.h>
#include <math.h>
#include <stdint.h>

#define DM 3072
#define BB 2
#define SSEQ 1024
#define NH 24
#define HD 128
#define MROWS (BB*SSEQ)   // 2048

// Scratch (device globals: no allocations allowed)
__device__ float g_q[MROWS*DM];
__device__ float g_k[MROWS*DM];
__device__ float g_v[MROWS*DM];
__device__ float g_ao[MROWS*DM];

__device__ __forceinline__ uint32_t f2tf32(float x) {
    uint32_t r;
    asm("cvt.rna.tf32.f32 %0, %1;" : "=r"(r) : "f"(x));
    return r;
}

__device__ __forceinline__ void mma_tf32(float c[4],
    uint32_t a0, uint32_t a1, uint32_t a2, uint32_t a3,
    uint32_t b0, uint32_t b1)
{
    asm volatile(
        "mma.sync.aligned.m16n8k8.row.col.f32.tf32.tf32.f32 "
        "{%0,%1,%2,%3}, {%4,%5,%6,%7}, {%8,%9}, {%0,%1,%2,%3};"
        : "+f"(c[0]), "+f"(c[1]), "+f"(c[2]), "+f"(c[3])
        : "r"(a0), "r"(a1), "r"(a2), "r"(a3), "r"(b0), "r"(b1));
}

// ---------------------------------------------------------------------------
// tf32 GEMM, double-buffered. Y[m,n] = sum_k X[m,k] * W[n,k]
// Fused over up to 3 weight/output pairs selected by blockIdx.x/24.
// CTA tile 128x128x16, 8 warps (4m x 2n), warp tile 32x64.
// ---------------------------------------------------------------------------
#define PADK 20

#define GEMM_STORE(buf) do { \
    As[buf][lrow*PADK + lc4 + 0] = f2tf32(ax0.x); \
    As[buf][lrow*PADK + lc4 + 1] = f2tf32(ax0.y); \
    As[buf][lrow*PADK + lc4 + 2] = f2tf32(ax0.z); \
    As[buf][lrow*PADK + lc4 + 3] = f2tf32(ax0.w); \
    As[buf][(lrow+64)*PADK + lc4 + 0] = f2tf32(ax1.x); \
    As[buf][(lrow+64)*PADK + lc4 + 1] = f2tf32(ax1.y); \
    As[buf][(lrow+64)*PADK + lc4 + 2] = f2tf32(ax1.z); \
    As[buf][(lrow+64)*PADK + lc4 + 3] = f2tf32(ax1.w); \
    Bs[buf][lrow*PADK + lc4 + 0] = f2tf32(bx0.x); \
    Bs[buf][lrow*PADK + lc4 + 1] = f2tf32(bx0.y); \
    Bs[buf][lrow*PADK + lc4 + 2] = f2tf32(bx0.z); \
    Bs[buf][lrow*PADK + lc4 + 3] = f2tf32(bx0.w); \
    Bs[buf][(lrow+64)*PADK + lc4 + 0] = f2tf32(bx1.x); \
    Bs[buf][(lrow+64)*PADK + lc4 + 1] = f2tf32(bx1.y); \
    Bs[buf][(lrow+64)*PADK + lc4 + 2] = f2tf32(bx1.z); \
    Bs[buf][(lrow+64)*PADK + lc4 + 3] = f2tf32(bx1.w); \
} while (0)

__global__ __launch_bounds__(256, 2) void tf32_gemm_kernel(
    const float* __restrict__ X,
    const float* __restrict__ Wa, const float* __restrict__ Wb, const float* __restrict__ Wc,
    float* __restrict__ Ya, float* __restrict__ Yb, float* __restrict__ Yc)
{
    __shared__ uint32_t As[2][128 * PADK];
    __shared__ uint32_t Bs[2][128 * PADK];

    const int t    = threadIdx.x;
    const int lane = t & 31;
    const int w    = t >> 5;
    const int warp_m = (w >> 1) * 32;
    const int warp_n = (w & 1) * 64;
    const int bx   = blockIdx.x;
    const int wsel = bx / 24;
    const float* W = (wsel == 0) ? Wa : ((wsel == 1) ? Wb : Wc);
    float*       Y = (wsel == 0) ? Ya : ((wsel == 1) ? Yb : Yc);
    const int bm = blockIdx.y * 128;
    const int bn = (bx - wsel * 24) * 128;

    const int lrow = t >> 2;
    const int lc4  = (t & 3) * 4;

    const float* xp = X + (size_t)(bm + lrow) * DM + lc4;
    const float* wp = W + (size_t)(bn + lrow) * DM + lc4;

    float4 ax0 = *(const float4*)(xp);
    float4 ax1 = *(const float4*)(xp + (size_t)64 * DM);
    float4 bx0 = *(const float4*)(wp);
    float4 bx1 = *(const float4*)(wp + (size_t)64 * DM);

    float c[2][8][4];
    #pragma unroll
    for (int mi = 0; mi < 2; mi++)
        #pragma unroll
        for (int ni = 0; ni < 8; ni++)
            #pragma unroll
            for (int j = 0; j < 4; j++) c[mi][ni][j] = 0.f;

    const int qd = lane >> 2;
    const int qk = lane & 3;
    const int NKT = DM / 16;   // 192

    GEMM_STORE(0);
    __syncthreads();

    for (int kt = 0; kt < NKT; kt++) {
        const int cur = kt & 1;
        if (kt + 1 < NKT) {
            const int off = (kt + 1) * 16;
            ax0 = *(const float4*)(xp + off);
            ax1 = *(const float4*)(xp + (size_t)64 * DM + off);
            bx0 = *(const float4*)(wp + off);
            bx1 = *(const float4*)(wp + (size_t)64 * DM + off);
        }

        #pragma unroll
        for (int ks = 0; ks < 2; ks++) {
            const int k0 = ks * 8 + qk;
            uint32_t a[2][4];
            #pragma unroll
            for (int mi = 0; mi < 2; mi++) {
                const int r0 = warp_m + mi*16 + qd;
                a[mi][0] = As[cur][r0*PADK + k0];
                a[mi][1] = As[cur][(r0+8)*PADK + k0];
                a[mi][2] = As[cur][r0*PADK + k0 + 4];
                a[mi][3] = As[cur][(r0+8)*PADK + k0 + 4];
            }
            #pragma unroll
            for (int ni = 0; ni < 8; ni++) {
                const int cn = warp_n + ni*8 + qd;
                uint32_t b0 = Bs[cur][cn*PADK + k0];
                uint32_t b1 = Bs[cur][cn*PADK + k0 + 4];
                mma_tf32(c[0][ni], a[0][0], a[0][1], a[0][2], a[0][3], b0, b1);
                mma_tf32(c[1][ni], a[1][0], a[1][1], a[1][2], a[1][3], b0, b1);
            }
        }

        if (kt + 1 < NKT) {
            GEMM_STORE(cur ^ 1);
        }
        __syncthreads();
    }

    #pragma unroll
    for (int mi = 0; mi < 2; mi++) {
        #pragma unroll
        for (int ni = 0; ni < 8; ni++) {
            const int row = bm + warp_m + mi*16 + qd;
            const int col = bn + warp_n + ni*8 + qk*2;
            float2 v0 = {c[mi][ni][0], c[mi][ni][1]};
            float2 v1 = {c[mi][ni][2], c[mi][ni][3]};
            *(float2*)(Y + (size_t)row * DM + col)       = v0;
            *(float2*)(Y + (size_t)(row + 8) * DM + col) = v1;
        }
    }
}

// ---------------------------------------------------------------------------
// Fused RMSNorm + RoPE on q and k. One block per (b*S+s, h), 128 threads.
// ---------------------------------------------------------------------------
__global__ __launch_bounds__(128) void norm_rope_kernel(
    float* __restrict__ q, float* __restrict__ k,
    const float* __restrict__ rope,
    const float* __restrict__ wq, const float* __restrict__ wk)
{
    const int row = blockIdx.x;
    const int h   = blockIdx.y;
    const int d   = threadIdx.x;
    const int s   = row & (SSEQ - 1);

    __shared__ float sh[128];
    __shared__ float red[4];

    float fr = rope[s * HD + d];
    float cs, sn;
    sincosf(fr, &sn, &cs);

    #pragma unroll
    for (int which = 0; which < 2; which++) {
        float* base = (which ? k : q) + (size_t)row * DM + h * HD;
        const float* w = which ? wk : wq;

        float x = base[d];
        float ssum = x * x;
        #pragma unroll
        for (int o = 16; o > 0; o >>= 1)
            ssum += __shfl_xor_sync(0xffffffffu, ssum, o);
        if ((d & 31) == 0) red[d >> 5] = ssum;
        __syncthreads();
        float tot = red[0] + red[1] + red[2] + red[3];
        float xn = x * rsqrtf(tot * (1.f/128.f) + 1e-6f) * w[d];
        sh[d] = xn;
        __syncthreads();
        float rot = (d < 64) ? -sh[d + 64] : sh[d - 64];
        base[d] = xn * cs + rot * sn;
        __syncthreads();
    }
}

// ---------------------------------------------------------------------------
// Flash attention with tf32 tensor cores.
// Block = 256 threads (8 warps), 64 q-rows, 16 k-tiles of 64.
// Scores: warp tile 16x32 (4m x 2n warps). PV: warp tile 16x64.
// Smem: Qs[64][136] tf32, KVs[64][136] tf32 (K then V), Ss[64][68] fp32,
//       sAlpha[64].
// ---------------------------------------------------------------------------
#define APQ 136
#define APS 68
#define ATT_SMEM ((64*APQ*2 + 64*APS + 64) * 4)

__global__ __launch_bounds__(256) void attn_kernel(
    const float* __restrict__ Q, const float* __restrict__ K,
    const float* __restrict__ V, float* __restrict__ O)
{
    extern __shared__ float smbuf[];
    uint32_t* Qs  = (uint32_t*)smbuf;
    uint32_t* KVs = Qs + 64 * APQ;
    float*    Ss  = (float*)(KVs + 64 * APQ);
    float* sAlpha = Ss + 64 * APS;

    const int t    = threadIdx.x;
    const int lane = t & 31;
    const int w    = t >> 5;
    const int qd   = lane >> 2;
    const int qk   = lane & 3;
    const int wm   = (w >> 1) * 16;   // mma row base (both phases)
    const int wn_s = (w & 1) * 32;    // scores col base
    const int wn_v = (w & 1) * 64;    // PV col base
    const int g    = t >> 2;          // softmax row
    const int q4   = t & 3;           // softmax lane-in-row

    const int qt = blockIdx.x;
    const int bh = blockIdx.y;
    const int b  = bh / NH;
    const int h  = bh % NH;
    const size_t base = (size_t)b * SSEQ * DM + (size_t)h * HD;
    const float* qb = Q + base;
    const float* kb = K + base;
    const float* vb = V + base;
    const int q0 = qt * 64;

    // Load Q (tf32, [row][d], stride 136)
    #pragma unroll
    for (int it = 0; it < 8; it++) {
        const int row = w + it * 8;
        float4 v4 = *(const float4*)(qb + (size_t)(q0 + row) * DM + lane * 4);
        uint4 u;
        u.x = f2tf32(v4.x); u.y = f2tf32(v4.y);
        u.z = f2tf32(v4.z); u.w = f2tf32(v4.w);
        *(uint4*)&Qs[row * APQ + lane * 4] = u;
    }

    float o[8][4];
    #pragma unroll
    for (int ni = 0; ni < 8; ni++)
        #pragma unroll
        for (int j = 0; j < 4; j++) o[ni][j] = 0.f;

    float m_r = -1e30f, l_r = 0.f;
    const float scale = 0.08838834764831845f;  // 1/sqrt(128)

    for (int kt = 0; kt < 16; kt++) {
        const int k0s = kt * 64;
        __syncthreads();   // #1: prior PV reads of Ss/KVs complete

        // Load K tile (tf32, [row][d])
        #pragma unroll
        for (int it = 0; it < 8; it++) {
            const int row = w + it * 8;
            float4 v4 = *(const float4*)(kb + (size_t)(k0s + row) * DM + lane * 4);
            uint4 u;
            u.x = f2tf32(v4.x); u.y = f2tf32(v4.y);
            u.z = f2tf32(v4.z); u.w = f2tf32(v4.w);
            *(uint4*)&KVs[row * APQ + lane * 4] = u;
        }
        __syncthreads();   // #2

        // Scores: S[64x64] = Q[64x128] * K^T
        float cs_[4][4];
        #pragma unroll
        for (int ni = 0; ni < 4; ni++)
            #pragma unroll
            for (int j = 0; j < 4; j++) cs_[ni][j] = 0.f;

        #pragma unroll
        for (int ks = 0; ks < 16; ks++) {
            const int k0 = ks * 8 + qk;
            uint32_t a0 = Qs[(wm + qd)     * APQ + k0];
            uint32_t a1 = Qs[(wm + qd + 8) * APQ + k0];
            uint32_t a2 = Qs[(wm + qd)     * APQ + k0 + 4];
            uint32_t a3 = Qs[(wm + qd + 8) * APQ + k0 + 4];
            #pragma unroll
            for (int ni = 0; ni < 4; ni++) {
                const int cn = wn_s + ni * 8 + qd;
                uint32_t b0 = KVs[cn * APQ + k0];
                uint32_t b1 = KVs[cn * APQ + k0 + 4];
                mma_tf32(cs_[ni], a0, a1, a2, a3, b0, b1);
            }
        }
        #pragma unroll
        for (int ni = 0; ni < 4; ni++) {
            const int col = wn_s + ni * 8 + 2 * qk;
            float2 s0 = {cs_[ni][0] * scale, cs_[ni][1] * scale};
            float2 s1 = {cs_[ni][2] * scale, cs_[ni][3] * scale};
            *(float2*)&Ss[(wm + qd)     * APS + col] = s0;
            *(float2*)&Ss[(wm + qd + 8) * APS + col] = s1;
        }
        __syncthreads();   // #3: scores visible; K reads done

        // Load V tile (tf32, overwrites K)
        #pragma unroll
        for (int it = 0; it < 8; it++) {
            const int row = w + it * 8;
            float4 v4 = *(const float4*)(vb + (size_t)(k0s + row) * DM + lane * 4);
            uint4 u;
            u.x = f2tf32(v4.x); u.y = f2tf32(v4.y);
            u.z = f2tf32(v4.z); u.w = f2tf32(v4.w);
            *(uint4*)&KVs[row * APQ + lane * 4] = u;
        }

        // Online softmax on row g (4 lanes per row)
        {
            float tmax = -1e30f;
            #pragma unroll
            for (int kk = q4; kk < 64; kk += 4)
                tmax = fmaxf(tmax, Ss[g * APS + kk]);
            tmax = fmaxf(tmax, __shfl_xor_sync(0xffffffffu, tmax, 1));
            tmax = fmaxf(tmax, __shfl_xor_sync(0xffffffffu, tmax, 2));
            float mnew  = fmaxf(m_r, tmax);
            float alpha = __expf(m_r - mnew);
            float psum  = 0.f;
            #pragma unroll
            for (int kk = q4; kk < 64; kk += 4) {
                float p = __expf(Ss[g * APS + kk] - mnew);
                Ss[g * APS + kk] = p;
                psum += p;
            }
            psum += __shfl_xor_sync(0xffffffffu, psum, 1);
            psum += __shfl_xor_sync(0xffffffffu, psum, 2);
            l_r = l_r * alpha + psum;
            m_r = mnew;
            if (q4 == 0) sAlpha[g] = alpha;
        }
        __syncthreads();   // #4: probs, V, alpha visible

        // Rescale accumulators
        {
            const float al0 = sAlpha[wm + qd];
            const float al1 = sAlpha[wm + qd + 8];
            #pragma unroll
            for (int ni = 0; ni < 8; ni++) {
                o[ni][0] *= al0; o[ni][1] *= al0;
                o[ni][2] *= al1; o[ni][3] *= al1;
            }
        }

        // PV: O[64x128] += P[64x64] * V[64x128]
        #pragma unroll
        for (int ks = 0; ks < 8; ks++) {
            const int k0 = ks * 8 + qk;
            uint32_t a0 = f2tf32(Ss[(wm + qd)     * APS + k0]);
            uint32_t a1 = f2tf32(Ss[(wm + qd + 8) * APS + k0]);
            uint32_t a2 = f2tf32(Ss[(wm + qd)     * APS + k0 + 4]);
            uint32_t a3 = f2tf32(Ss[(wm + qd + 8) * APS + k0 + 4]);
            #pragma unroll
            for (int ni = 0; ni < 8; ni++) {
                const int cn = wn_v + ni * 8 + qd;
                uint32_t b0 = KVs[k0 * APQ + cn];
                uint32_t b1 = KVs[(k0 + 4) * APQ + cn];
                mma_tf32(o[ni], a0, a1, a2, a3, b0, b1);
            }
        }
    }

    // Final normalization + write
    if (q4 == 0) sAlpha[g] = 1.f / l_r;
    __syncthreads();
    const float li0 = sAlpha[wm + qd];
    const float li1 = sAlpha[wm + qd + 8];
    #pragma unroll
    for (int ni = 0; ni < 8; ni++) {
        const int col = wn_v + ni * 8 + 2 * qk;
        float2 v0 = {o[ni][0] * li0, o[ni][1] * li0};
        float2 v1 = {o[ni][2] * li1, o[ni][3] * li1};
        *(float2*)(O + base + (size_t)(q0 + wm + qd)     * DM + col) = v0;
        *(float2*)(O + base + (size_t)(q0 + wm + qd + 8) * DM + col) = v1;
    }
}

// ---------------------------------------------------------------------------
extern "C" void kernel_launch(void* const* d_in, const int* in_sizes, int n_in,
                              void* d_out, int out_size)
{
    const float* hidden = (const float*)d_in[0];
    const float* rope   = (const float*)d_in[1];
    const float* Wq     = (const float*)d_in[2];
    const float* Wk     = (const float*)d_in[3];
    const float* Wv     = (const float*)d_in[4];
    const float* Wo     = (const float*)d_in[5];
    const float* nqw    = (const float*)d_in[6];
    const float* nkw    = (const float*)d_in[7];
    float* out = (float*)d_out;

    float *q, *k, *v, *ao;
    cudaGetSymbolAddress((void**)&q,  g_q);
    cudaGetSymbolAddress((void**)&k,  g_k);
    cudaGetSymbolAddress((void**)&v,  g_v);
    cudaGetSymbolAddress((void**)&ao, g_ao);

    // Fused QKV projection: grid.x covers 3 weight matrices
    tf32_gemm_kernel<<<dim3(72, 16), 256>>>(hidden, Wq, Wk, Wv, q, k, v);

    norm_rope_kernel<<<dim3(MROWS, NH), 128>>>(q, k, rope, nqw, nkw);

    cudaFuncSetAttribute(attn_kernel, cudaFuncAttributeMaxDynamicSharedMemorySize, ATT_SMEM);
    attn_kernel<<<dim3(SSEQ/64, BB*NH), 256, ATT_SMEM>>>(q, k, v, ao);

    // Output projection
    tf32_gemm_kernel<<<dim3(24, 16), 256>>>(ao, Wo, Wo, Wo, out, out, out);
}

// round 5
// speedup vs baseline: 3.7397x; 1.1806x over previous
#include <cuda_runtime.h>
#include <math.h>
#include <stdint.h>

#define DM 3072
#define BB 2
#define SSEQ 1024
#define NH 24
#define HD 128
#define MROWS (BB*SSEQ)   // 2048

// Scratch (device globals: no allocations allowed)
__device__ float g_q[MROWS*DM];
__device__ float g_k[MROWS*DM];
__device__ float g_v[MROWS*DM];
__device__ float g_ao[MROWS*DM];

__device__ __forceinline__ uint32_t smem_u32(const void* p) {
    uint32_t a;
    asm("{ .reg .u64 t; cvta.to.shared.u64 t, %1; cvt.u32.u64 %0, t; }"
        : "=r"(a) : "l"(p));
    return a;
}

__device__ __forceinline__ uint32_t f2tf32(float x) {
    uint32_t r;
    asm("cvt.rna.tf32.f32 %0, %1;" : "=r"(r) : "f"(x));
    return r;
}

__device__ __forceinline__ void mma_tf32(float c[4],
    uint32_t a0, uint32_t a1, uint32_t a2, uint32_t a3,
    uint32_t b0, uint32_t b1)
{
    asm volatile(
        "mma.sync.aligned.m16n8k8.row.col.f32.tf32.tf32.f32 "
        "{%0,%1,%2,%3}, {%4,%5,%6,%7}, {%8,%9}, {%0,%1,%2,%3};"
        : "+f"(c[0]), "+f"(c[1]), "+f"(c[2]), "+f"(c[3])
        : "r"(a0), "r"(a1), "r"(a2), "r"(a3), "r"(b0), "r"(b1));
}

__device__ __forceinline__ void ldsm_x4(
    uint32_t& r0, uint32_t& r1, uint32_t& r2, uint32_t& r3, uint32_t addr)
{
    asm volatile("ldmatrix.sync.aligned.m8n8.x4.shared.b16 {%0,%1,%2,%3}, [%4];"
        : "=r"(r0), "=r"(r1), "=r"(r2), "=r"(r3) : "r"(addr));
}

// ---------------------------------------------------------------------------
// tf32 GEMM, double-buffered, LDSM-fed. Y[m,n] = sum_k X[m,k] * W[n,k]
// CTA tile 128x128x16, 8 warps (4m x 2n), warp tile 32x64.
// Fused over up to 3 weight/output pairs via blockIdx.x/24.
// ---------------------------------------------------------------------------
#define PADK 20
#define BUFW (128 * PADK)          // words per buffer
#define BUFB (BUFW * 4)            // bytes per buffer

__global__ __launch_bounds__(256, 2) void tf32_gemm_kernel(
    const float* __restrict__ X,
    const float* __restrict__ Wa, const float* __restrict__ Wb, const float* __restrict__ Wc,
    float* __restrict__ Ya, float* __restrict__ Yb, float* __restrict__ Yc)
{
    __shared__ uint32_t As[2][BUFW];
    __shared__ uint32_t Bs[2][BUFW];

    const int t    = threadIdx.x;
    const int lane = t & 31;
    const int w    = t >> 5;
    const int warp_m = (w >> 1) * 32;
    const int warp_n = (w & 1) * 64;
    const int bx   = blockIdx.x;
    const int wsel = bx / 24;
    const float* W = (wsel == 0) ? Wa : ((wsel == 1) ? Wb : Wc);
    float*       Y = (wsel == 0) ? Ya : ((wsel == 1) ? Yb : Yc);
    const int bm = blockIdx.y * 128;
    const int bn = (bx - wsel * 24) * 128;

    const int lrow = t >> 2;       // 0..63
    const int lc4  = (t & 3) * 4;  // 0,4,8,12

    const float* xp = X + (size_t)(bm + lrow) * DM + lc4;
    const float* wp = W + (size_t)(bn + lrow) * DM + lc4;

    const uint32_t sAbase = smem_u32(&As[0][0]);
    const uint32_t sBbase = smem_u32(&Bs[0][0]);

    // ldmatrix addresses (per-lane), buffer 0, kstep 0:
    // A tiles (mi): rows warp_m+mi*16 + ((l>>3)&1)*8 + (l&7); k part = (l>>4)*4
    // B tiles (np): cols warp_n+np*16 + (l>>4)*8 + (l&7);     k part = ((l>>3)&1)*4
    const int l7 = lane & 7;
    const int aArow = warp_m + ((lane >> 3) & 1) * 8 + l7;
    const int aAk   = (lane >> 4) * 4;
    uint32_t aA[2];
    aA[0] = sAbase + (uint32_t)((aArow)      * PADK + aAk) * 4u;
    aA[1] = sAbase + (uint32_t)((aArow + 16) * PADK + aAk) * 4u;
    const int aBcol = warp_n + (lane >> 4) * 8 + l7;
    const int aBk   = ((lane >> 3) & 1) * 4;
    uint32_t aB[4];
    #pragma unroll
    for (int np = 0; np < 4; np++)
        aB[np] = sBbase + (uint32_t)((aBcol + np * 16) * PADK + aBk) * 4u;

    float c[2][8][4];
    #pragma unroll
    for (int mi = 0; mi < 2; mi++)
        #pragma unroll
        for (int ni = 0; ni < 8; ni++)
            #pragma unroll
            for (int j = 0; j < 4; j++) c[mi][ni][j] = 0.f;

    const int qd = lane >> 2;
    const int qk = lane & 3;
    const int NKT = DM / 16;   // 192

    // k-tile store: vectorized STS.128 (addresses 16B-aligned)
    #define GSTORE(buf, a0v, a1v, b0v, b1v) do { \
        uint4 ua0 = {f2tf32((a0v).x), f2tf32((a0v).y), f2tf32((a0v).z), f2tf32((a0v).w)}; \
        uint4 ua1 = {f2tf32((a1v).x), f2tf32((a1v).y), f2tf32((a1v).z), f2tf32((a1v).w)}; \
        uint4 ub0 = {f2tf32((b0v).x), f2tf32((b0v).y), f2tf32((b0v).z), f2tf32((b0v).w)}; \
        uint4 ub1 = {f2tf32((b1v).x), f2tf32((b1v).y), f2tf32((b1v).z), f2tf32((b1v).w)}; \
        *(uint4*)&As[buf][lrow*PADK + lc4]      = ua0; \
        *(uint4*)&As[buf][(lrow+64)*PADK + lc4] = ua1; \
        *(uint4*)&Bs[buf][lrow*PADK + lc4]      = ub0; \
        *(uint4*)&Bs[buf][(lrow+64)*PADK + lc4] = ub1; \
    } while (0)

    float4 ax0 = *(const float4*)(xp);
    float4 ax1 = *(const float4*)(xp + (size_t)64 * DM);
    float4 bx0 = *(const float4*)(wp);
    float4 bx1 = *(const float4*)(wp + (size_t)64 * DM);
    GSTORE(0, ax0, ax1, bx0, bx1);
    __syncthreads();

    for (int kt = 0; kt < NKT; kt++) {
        const int cur = kt & 1;
        const uint32_t boff = (uint32_t)cur * (uint32_t)BUFB;

        if (kt + 1 < NKT) {
            const int off = (kt + 1) * 16;
            ax0 = *(const float4*)(xp + off);
            ax1 = *(const float4*)(xp + (size_t)64 * DM + off);
            bx0 = *(const float4*)(wp + off);
            bx1 = *(const float4*)(wp + (size_t)64 * DM + off);
        }

        #pragma unroll
        for (int ks = 0; ks < 2; ks++) {
            const uint32_t koff = boff + (uint32_t)ks * 32u;  // 8 tf32 = 32 bytes
            uint32_t a[2][4];
            ldsm_x4(a[0][0], a[0][1], a[0][2], a[0][3], aA[0] + koff);
            ldsm_x4(a[1][0], a[1][1], a[1][2], a[1][3], aA[1] + koff);
            #pragma unroll
            for (int np = 0; np < 4; np++) {
                uint32_t b0, b1, b2, b3;
                ldsm_x4(b0, b1, b2, b3, aB[np] + koff);
                mma_tf32(c[0][2*np],   a[0][0], a[0][1], a[0][2], a[0][3], b0, b1);
                mma_tf32(c[1][2*np],   a[1][0], a[1][1], a[1][2], a[1][3], b0, b1);
                mma_tf32(c[0][2*np+1], a[0][0], a[0][1], a[0][2], a[0][3], b2, b3);
                mma_tf32(c[1][2*np+1], a[1][0], a[1][1], a[1][2], a[1][3], b2, b3);
            }
        }

        if (kt + 1 < NKT) {
            GSTORE(cur ^ 1, ax0, ax1, bx0, bx1);
        }
        __syncthreads();
    }

    #pragma unroll
    for (int mi = 0; mi < 2; mi++) {
        #pragma unroll
        for (int ni = 0; ni < 8; ni++) {
            const int row = bm + warp_m + mi*16 + qd;
            const int col = bn + warp_n + ni*8 + qk*2;
            float2 v0 = {c[mi][ni][0], c[mi][ni][1]};
            float2 v1 = {c[mi][ni][2], c[mi][ni][3]};
            *(float2*)(Y + (size_t)row * DM + col)       = v0;
            *(float2*)(Y + (size_t)(row + 8) * DM + col) = v1;
        }
    }
}

// ---------------------------------------------------------------------------
// Fused RMSNorm + RoPE on q and k. One block per (b*S+s, h), 128 threads.
// ---------------------------------------------------------------------------
__global__ __launch_bounds__(128) void norm_rope_kernel(
    float* __restrict__ q, float* __restrict__ k,
    const float* __restrict__ rope,
    const float* __restrict__ wq, const float* __restrict__ wk)
{
    const int row = blockIdx.x;
    const int h   = blockIdx.y;
    const int d   = threadIdx.x;
    const int s   = row & (SSEQ - 1);

    __shared__ float sh[128];
    __shared__ float red[4];

    float fr = rope[s * HD + d];
    float cs, sn;
    sincosf(fr, &sn, &cs);

    #pragma unroll
    for (int which = 0; which < 2; which++) {
        float* base = (which ? k : q) + (size_t)row * DM + h * HD;
        const float* w = which ? wk : wq;

        float x = base[d];
        float ssum = x * x;
        #pragma unroll
        for (int o = 16; o > 0; o >>= 1)
            ssum += __shfl_xor_sync(0xffffffffu, ssum, o);
        if ((d & 31) == 0) red[d >> 5] = ssum;
        __syncthreads();
        float tot = red[0] + red[1] + red[2] + red[3];
        float xn = x * rsqrtf(tot * (1.f/128.f) + 1e-6f) * w[d];
        sh[d] = xn;
        __syncthreads();
        float rot = (d < 64) ? -sh[d + 64] : sh[d - 64];
        base[d] = xn * cs + rot * sn;
        __syncthreads();
    }
}

// ---------------------------------------------------------------------------
// Flash attention with tf32 legacy mma (unchanged from Round 3 passing run).
// ---------------------------------------------------------------------------
#define APQ 136
#define APS 68
#define ATT_SMEM ((64*APQ*2 + 64*APS + 64) * 4)

__global__ __launch_bounds__(256) void attn_kernel(
    const float* __restrict__ Q, const float* __restrict__ K,
    const float* __restrict__ V, float* __restrict__ O)
{
    extern __shared__ float smbuf[];
    uint32_t* Qs  = (uint32_t*)smbuf;
    uint32_t* KVs = Qs + 64 * APQ;
    float*    Ss  = (float*)(KVs + 64 * APQ);
    float* sAlpha = Ss + 64 * APS;

    const int t    = threadIdx.x;
    const int lane = t & 31;
    const int w    = t >> 5;
    const int qd   = lane >> 2;
    const int qk   = lane & 3;
    const int wm   = (w >> 1) * 16;
    const int wn_s = (w & 1) * 32;
    const int wn_v = (w & 1) * 64;
    const int g    = t >> 2;
    const int q4   = t & 3;

    const int qt = blockIdx.x;
    const int bh = blockIdx.y;
    const int b  = bh / NH;
    const int h  = bh % NH;
    const size_t base = (size_t)b * SSEQ * DM + (size_t)h * HD;
    const float* qb = Q + base;
    const float* kb = K + base;
    const float* vb = V + base;
    const int q0 = qt * 64;

    #pragma unroll
    for (int it = 0; it < 8; it++) {
        const int row = w + it * 8;
        float4 v4 = *(const float4*)(qb + (size_t)(q0 + row) * DM + lane * 4);
        uint4 u;
        u.x = f2tf32(v4.x); u.y = f2tf32(v4.y);
        u.z = f2tf32(v4.z); u.w = f2tf32(v4.w);
        *(uint4*)&Qs[row * APQ + lane * 4] = u;
    }

    float o[8][4];
    #pragma unroll
    for (int ni = 0; ni < 8; ni++)
        #pragma unroll
        for (int j = 0; j < 4; j++) o[ni][j] = 0.f;

    float m_r = -1e30f, l_r = 0.f;
    const float scale = 0.08838834764831845f;

    for (int kt = 0; kt < 16; kt++) {
        const int k0s = kt * 64;
        __syncthreads();

        #pragma unroll
        for (int it = 0; it < 8; it++) {
            const int row = w + it * 8;
            float4 v4 = *(const float4*)(kb + (size_t)(k0s + row) * DM + lane * 4);
            uint4 u;
            u.x = f2tf32(v4.x); u.y = f2tf32(v4.y);
            u.z = f2tf32(v4.z); u.w = f2tf32(v4.w);
            *(uint4*)&KVs[row * APQ + lane * 4] = u;
        }
        __syncthreads();

        float cs_[4][4];
        #pragma unroll
        for (int ni = 0; ni < 4; ni++)
            #pragma unroll
            for (int j = 0; j < 4; j++) cs_[ni][j] = 0.f;

        #pragma unroll
        for (int ks = 0; ks < 16; ks++) {
            const int k0 = ks * 8 + qk;
            uint32_t a0 = Qs[(wm + qd)     * APQ + k0];
            uint32_t a1 = Qs[(wm + qd + 8) * APQ + k0];
            uint32_t a2 = Qs[(wm + qd)     * APQ + k0 + 4];
            uint32_t a3 = Qs[(wm + qd + 8) * APQ + k0 + 4];
            #pragma unroll
            for (int ni = 0; ni < 4; ni++) {
                const int cn = wn_s + ni * 8 + qd;
                uint32_t b0 = KVs[cn * APQ + k0];
                uint32_t b1 = KVs[cn * APQ + k0 + 4];
                mma_tf32(cs_[ni], a0, a1, a2, a3, b0, b1);
            }
        }
        #pragma unroll
        for (int ni = 0; ni < 4; ni++) {
            const int col = wn_s + ni * 8 + 2 * qk;
            float2 s0 = {cs_[ni][0] * scale, cs_[ni][1] * scale};
            float2 s1 = {cs_[ni][2] * scale, cs_[ni][3] * scale};
            *(float2*)&Ss[(wm + qd)     * APS + col] = s0;
            *(float2*)&Ss[(wm + qd + 8) * APS + col] = s1;
        }
        __syncthreads();

        #pragma unroll
        for (int it = 0; it < 8; it++) {
            const int row = w + it * 8;
            float4 v4 = *(const float4*)(vb + (size_t)(k0s + row) * DM + lane * 4);
            uint4 u;
            u.x = f2tf32(v4.x); u.y = f2tf32(v4.y);
            u.z = f2tf32(v4.z); u.w = f2tf32(v4.w);
            *(uint4*)&KVs[row * APQ + lane * 4] = u;
        }

        {
            float tmax = -1e30f;
            #pragma unroll
            for (int kk = q4; kk < 64; kk += 4)
                tmax = fmaxf(tmax, Ss[g * APS + kk]);
            tmax = fmaxf(tmax, __shfl_xor_sync(0xffffffffu, tmax, 1));
            tmax = fmaxf(tmax, __shfl_xor_sync(0xffffffffu, tmax, 2));
            float mnew  = fmaxf(m_r, tmax);
            float alpha = __expf(m_r - mnew);
            float psum  = 0.f;
            #pragma unroll
            for (int kk = q4; kk < 64; kk += 4) {
                float p = __expf(Ss[g * APS + kk] - mnew);
                Ss[g * APS + kk] = p;
                psum += p;
            }
            psum += __shfl_xor_sync(0xffffffffu, psum, 1);
            psum += __shfl_xor_sync(0xffffffffu, psum, 2);
            l_r = l_r * alpha + psum;
            m_r = mnew;
            if (q4 == 0) sAlpha[g] = alpha;
        }
        __syncthreads();

        {
            const float al0 = sAlpha[wm + qd];
            const float al1 = sAlpha[wm + qd + 8];
            #pragma unroll
            for (int ni = 0; ni < 8; ni++) {
                o[ni][0] *= al0; o[ni][1] *= al0;
                o[ni][2] *= al1; o[ni][3] *= al1;
            }
        }

        #pragma unroll
        for (int ks = 0; ks < 8; ks++) {
            const int k0 = ks * 8 + qk;
            uint32_t a0 = f2tf32(Ss[(wm + qd)     * APS + k0]);
            uint32_t a1 = f2tf32(Ss[(wm + qd + 8) * APS + k0]);
            uint32_t a2 = f2tf32(Ss[(wm + qd)     * APS + k0 + 4]);
            uint32_t a3 = f2tf32(Ss[(wm + qd + 8) * APS + k0 + 4]);
            #pragma unroll
            for (int ni = 0; ni < 8; ni++) {
                const int cn = wn_v + ni * 8 + qd;
                uint32_t b0 = KVs[k0 * APQ + cn];
                uint32_t b1 = KVs[(k0 + 4) * APQ + cn];
                mma_tf32(o[ni], a0, a1, a2, a3, b0, b1);
            }
        }
    }

    if (q4 == 0) sAlpha[g] = 1.f / l_r;
    __syncthreads();
    const float li0 = sAlpha[wm + qd];
    const float li1 = sAlpha[wm + qd + 8];
    #pragma unroll
    for (int ni = 0; ni < 8; ni++) {
        const int col = wn_v + ni * 8 + 2 * qk;
        float2 v0 = {o[ni][0] * li0, o[ni][1] * li0};
        float2 v1 = {o[ni][2] * li1, o[ni][3] * li1};
        *(float2*)(O + base + (size_t)(q0 + wm + qd)     * DM + col) = v0;
        *(float2*)(O + base + (size_t)(q0 + wm + qd + 8) * DM + col) = v1;
    }
}

// ---------------------------------------------------------------------------
extern "C" void kernel_launch(void* const* d_in, const int* in_sizes, int n_in,
                              void* d_out, int out_size)
{
    const float* hidden = (const float*)d_in[0];
    const float* rope   = (const float*)d_in[1];
    const float* Wq     = (const float*)d_in[2];
    const float* Wk     = (const float*)d_in[3];
    const float* Wv     = (const float*)d_in[4];
    const float* Wo     = (const float*)d_in[5];
    const float* nqw    = (const float*)d_in[6];
    const float* nkw    = (const float*)d_in[7];
    float* out = (float*)d_out;

    float *q, *k, *v, *ao;
    cudaGetSymbolAddress((void**)&q,  g_q);
    cudaGetSymbolAddress((void**)&k,  g_k);
    cudaGetSymbolAddress((void**)&v,  g_v);
    cudaGetSymbolAddress((void**)&ao, g_ao);

    // Fused QKV projection
    tf32_gemm_kernel<<<dim3(72, 16), 256>>>(hidden, Wq, Wk, Wv, q, k, v);

    norm_rope_kernel<<<dim3(MROWS, NH), 128>>>(q, k, rope, nqw, nkw);

    cudaFuncSetAttribute(attn_kernel, cudaFuncAttributeMaxDynamicSharedMemorySize, ATT_SMEM);
    attn_kernel<<<dim3(SSEQ/64, BB*NH), 256, ATT_SMEM>>>(q, k, v, ao);

    // Output projection
    tf32_gemm_kernel<<<dim3(24, 16), 256>>>(ao, Wo, Wo, Wo, out, out, out);
}